// round 5
// baseline (speedup 1.0000x reference)
#include <cuda_runtime.h>
#include <cstdint>

#define CROP 14
#define B_ 4
#define N_ 256
#define H_ 256
#define W_ 256
#define C_ 256
#define CQ (C_ / 4)          // float4 quads per pixel = 64

// 196 positions per box, split across 7 CTAs of 28 positions each.
#define PARTS 7
#define POS_PER_PART 28
#define NGROUPS (POS_PER_PART / 4)   // 7 groups of 4 positions

#define CP_ASYNC16(smem_u32, gptr)                                            \
    asm volatile("cp.async.cg.shared.global [%0], [%1], 16;"                  \
                 :: "r"(smem_u32), "l"(gptr))
#define CP_COMMIT()  asm volatile("cp.async.commit_group;")
#define CP_WAIT1()   asm volatile("cp.async.wait_group 1;")

__global__ __launch_bounds__(256) void roi_align_kernel(
    const float* __restrict__ boxes,
    const float* __restrict__ fpn,
    float* __restrict__ out)
{
    // Phase-1: per-axis sampling grids
    __shared__ int   s_i0[2][CROP];
    __shared__ int   s_i1[2][CROP];
    __shared__ float s_w [2][CROP];
    __shared__ float s_v [2][CROP];
    // Phase-2: per-position packed corner offsets (float4 units) + weights
    __shared__ int4   s_off[POS_PER_PART];   // (tl, tr, bl, br)
    __shared__ float4 s_wv [POS_PER_PART];   // (w00, w01, w10, w11)
    // cp.async ping-pong stage: [buf][pos-in-group][corner][quad]
    __shared__ float4 s_buf[2][4][4][CQ];    // 32 KB

    const int blk  = blockIdx.y;       // box index: b * N_ + n (box-major)
    const int part = blockIdx.x;       // 0..6
    const int b    = blk >> 8;
    const int base = part * POS_PER_PART;

    const float4 bx = ((const float4*)boxes)[blk];   // (x1, y1, x2, y2)

    const int tid = threadIdx.x;
    if (tid < 2 * CROP) {
        const int axis = tid / CROP;   // 0 = y, 1 = x
        const int i    = tid % CROP;
        const float lo = (axis == 0) ? bx.y : bx.x;
        const float hi = (axis == 0) ? bx.w : bx.z;
        // Replicate reference math in float32:
        //   n1 = lo/255 ; n2 = (hi-1)/255 ; t = i/13 ; s = (n1 + (n2-n1)*t) * 255
        const float t  = (float)i / 13.0f;
        const float n1 = lo / 255.0f;
        const float n2 = (hi - 1.0f) / 255.0f;
        const float s  = (n1 + (n2 - n1) * t) * 255.0f;
        const float valid = (s >= 0.0f && s <= 255.0f) ? 1.0f : 0.0f;
        const float f0 = floorf(s);
        const float w  = s - f0;
        int i0 = (int)f0;
        int i1 = i0 + 1;
        i0 = min(max(i0, 0), H_ - 1);
        i1 = min(max(i1, 0), H_ - 1);
        s_i0[axis][i] = i0;
        s_i1[axis][i] = i1;
        s_w [axis][i] = w;
        s_v [axis][i] = valid;
    }
    __syncthreads();

    if (tid < POS_PER_PART) {
        const int pos = base + tid;
        const int py  = pos / CROP;
        const int px  = pos - py * CROP;
        const int   y0 = s_i0[0][py], y1 = s_i1[0][py];
        const int   x0 = s_i0[1][px], x1 = s_i1[1][px];
        const float wy = s_w[0][py],  wx = s_w[1][px];
        const float v  = s_v[0][py] * s_v[1][px];
        s_off[tid] = make_int4((y0 * W_ + x0) * CQ, (y0 * W_ + x1) * CQ,
                               (y1 * W_ + x0) * CQ, (y1 * W_ + x1) * CQ);
        s_wv[tid]  = make_float4((1.0f - wy) * (1.0f - wx) * v,
                                 (1.0f - wy) * wx * v,
                                 wy * (1.0f - wx) * v,
                                 wy * wx * v);
    }
    __syncthreads();

    const float4* img  = (const float4*)(fpn) + (size_t)b * (H_ * W_ * CQ);
    float4*       outp = (float4*)(out) + ((size_t)blk * (CROP * CROP) + base) * CQ;

    const int sub = tid >> 6;   // position within group (0..3)
    const int q   = tid & 63;   // float4 index within C

    // Per-thread private stage slots (each thread only touches its own bytes,
    // so the whole pipeline needs NO barriers).
    uint32_t my_slot[2];
    my_slot[0] = (uint32_t)__cvta_generic_to_shared(&s_buf[0][sub][0][q]);
    my_slot[1] = (uint32_t)__cvta_generic_to_shared(&s_buf[1][sub][0][q]);
    const uint32_t cstride = (uint32_t)(CQ * sizeof(float4));  // corner stride

    // Stage group g into buffer s: 4 fire-and-forget 16B copies.
    auto stage = [&](int g, int s) {
        const int4 o = s_off[g * 4 + sub];
        const uint32_t d = my_slot[s];
        CP_ASYNC16(d + 0 * cstride, img + o.x + q);
        CP_ASYNC16(d + 1 * cstride, img + o.y + q);
        CP_ASYNC16(d + 2 * cstride, img + o.z + q);
        CP_ASYNC16(d + 3 * cstride, img + o.w + q);
    };

    stage(0, 0); CP_COMMIT();
    stage(1, 1); CP_COMMIT();

    #pragma unroll
    for (int i = 0; i < NGROUPS; i++) {
        CP_WAIT1();                       // group i has landed in buf[i&1]

        const int s = i & 1;
        const float4 tl = s_buf[s][sub][0][q];
        const float4 tr = s_buf[s][sub][1][q];
        const float4 bl = s_buf[s][sub][2][q];
        const float4 br = s_buf[s][sub][3][q];
        const float4 w  = s_wv[i * 4 + sub];

        float4 r;
        r.x = tl.x * w.x + tr.x * w.y + bl.x * w.z + br.x * w.w;
        r.y = tl.y * w.x + tr.y * w.y + bl.y * w.z + br.y * w.w;
        r.z = tl.z * w.x + tr.z * w.y + bl.z * w.z + br.z * w.w;
        r.w = tl.w * w.x + tr.w * w.y + bl.w * w.z + br.w * w.w;

        // Streaming store: output is never re-read; keep the image L2-resident.
        __stcs(&outp[(i * 4 + sub) * CQ + q], r);

        // Refill the buffer we just consumed (reads above are already in
        // registers via data dependence before these async writes land).
        if (i + 2 < NGROUPS) stage(i + 2, s);
        CP_COMMIT();                      // commit every iter to keep counts aligned
    }
}

extern "C" void kernel_launch(void* const* d_in, const int* in_sizes, int n_in,
                              void* d_out, int out_size) {
    const float* boxes = (const float*)d_in[0];
    const float* fpn   = (const float*)d_in[1];
    if (n_in >= 2 && in_sizes[0] > in_sizes[1]) {
        boxes = (const float*)d_in[1];
        fpn   = (const float*)d_in[0];
    }
    dim3 grid(PARTS, B_ * N_);
    roi_align_kernel<<<grid, 256>>>(boxes, fpn, (float*)d_out);
}

// round 6
// speedup vs baseline: 1.0118x; 1.0118x over previous
#include <cuda_runtime.h>

#define CROP 14
#define B_ 4
#define N_ 256
#define H_ 256
#define W_ 256
#define C_ 256
#define CQ (C_ / 4)          // float4 quads per pixel = 64

// 196 positions per box, split across 7 work items of 28 positions each.
#define PARTS 7
#define POS_PER_PART 28
#define TOTAL_ITEMS (B_ * N_ * PARTS)   // 7168

// Persistent grid: exactly fills the chip (148 SMs x 8 CTAs).
#define NUM_SMS 148
#define CTAS_PER_SM 8
#define GRID_CTAS (NUM_SMS * CTAS_PER_SM)   // 1184

__global__ __launch_bounds__(256, CTAS_PER_SM) void roi_align_kernel(
    const float* __restrict__ boxes,
    const float* __restrict__ fpn,
    float* __restrict__ out)
{
    // Per-box sampling grids (y and x axes)
    __shared__ int   s_i0[2][CROP];
    __shared__ int   s_i1[2][CROP];
    __shared__ float s_w [2][CROP];
    __shared__ float s_v [2][CROP];
    // Per-position packed corner offsets (float4 units) + combined weights
    __shared__ int4   s_off[POS_PER_PART];   // (tl, tr, bl, br)
    __shared__ float4 s_wv [POS_PER_PART];   // (w00, w01, w10, w11)

    const int tid = threadIdx.x;
    const int sub = tid >> 6;   // 4 positions in flight across the CTA
    const int q   = tid & 63;   // float4 index within C

    // Grid-stride over work items. item = blk * PARTS + part, so chip-wide
    // order is box-major (same L2 locality as the 7x1024 grid), but with no
    // wave-transition bubbles: each CTA rolls straight into its next item.
    for (int item = blockIdx.x; item < TOTAL_ITEMS; item += GRID_CTAS) {
        const int blk  = item / PARTS;      // box index: b * N_ + n
        const int part = item - blk * PARTS;
        const int b    = blk >> 8;          // N_ = 256
        const int base = part * POS_PER_PART;

        const float4 bx = ((const float4*)boxes)[blk];   // (x1, y1, x2, y2)

        __syncthreads();   // smem from previous item fully consumed
        if (tid < 2 * CROP) {
            const int axis = tid / CROP;   // 0 = y, 1 = x
            const int i    = tid % CROP;
            const float lo = (axis == 0) ? bx.y : bx.x;
            const float hi = (axis == 0) ? bx.w : bx.z;
            // Replicate reference math in float32:
            //   n1 = lo/255 ; n2 = (hi-1)/255 ; t = i/13 ; s = (n1+(n2-n1)t)*255
            const float t  = (float)i / 13.0f;
            const float n1 = lo / 255.0f;
            const float n2 = (hi - 1.0f) / 255.0f;
            const float s  = (n1 + (n2 - n1) * t) * 255.0f;
            const float valid = (s >= 0.0f && s <= 255.0f) ? 1.0f : 0.0f;
            const float f0 = floorf(s);
            const float w  = s - f0;
            int i0 = (int)f0;
            int i1 = i0 + 1;
            i0 = min(max(i0, 0), H_ - 1);
            i1 = min(max(i1, 0), H_ - 1);
            s_i0[axis][i] = i0;
            s_i1[axis][i] = i1;
            s_w [axis][i] = w;
            s_v [axis][i] = valid;
        }
        __syncthreads();

        if (tid < POS_PER_PART) {
            const int pos = base + tid;
            const int py  = pos / CROP;
            const int px  = pos - py * CROP;
            const int   y0 = s_i0[0][py], y1 = s_i1[0][py];
            const int   x0 = s_i0[1][px], x1 = s_i1[1][px];
            const float wy = s_w[0][py],  wx = s_w[1][px];
            const float v  = s_v[0][py] * s_v[1][px];
            s_off[tid] = make_int4((y0 * W_ + x0) * CQ, (y0 * W_ + x1) * CQ,
                                   (y1 * W_ + x0) * CQ, (y1 * W_ + x1) * CQ);
            s_wv[tid]  = make_float4((1.0f - wy) * (1.0f - wx) * v,
                                     (1.0f - wy) * wx * v,
                                     wy * (1.0f - wx) * v,
                                     wy * wx * v);
        }
        __syncthreads();

        const float4* img  = (const float4*)(fpn) + (size_t)b * (H_ * W_ * CQ);
        float4* outp = (float4*)(out) + ((size_t)blk * (CROP * CROP) + base) * CQ;

        #pragma unroll 2
        for (int pb = 0; pb < POS_PER_PART; pb += 4) {
            const int p = pb + sub;
            const int4   o = s_off[p];
            const float4 w = s_wv[p];

            const float4 tl = img[o.x + q];
            const float4 tr = img[o.y + q];
            const float4 bl = img[o.z + q];
            const float4 br = img[o.w + q];

            float4 r;
            r.x = tl.x * w.x + tr.x * w.y + bl.x * w.z + br.x * w.w;
            r.y = tl.y * w.x + tr.y * w.y + bl.y * w.z + br.y * w.w;
            r.z = tl.z * w.x + tr.z * w.y + bl.z * w.z + br.z * w.w;
            r.w = tl.w * w.x + tr.w * w.y + bl.w * w.z + br.w * w.w;

            // Streaming store: output is never re-read; keep image L2-resident.
            __stcs(&outp[p * CQ + q], r);
        }
    }
}

extern "C" void kernel_launch(void* const* d_in, const int* in_sizes, int n_in,
                              void* d_out, int out_size) {
    const float* boxes = (const float*)d_in[0];
    const float* fpn   = (const float*)d_in[1];
    if (n_in >= 2 && in_sizes[0] > in_sizes[1]) {
        boxes = (const float*)d_in[1];
        fpn   = (const float*)d_in[0];
    }
    roi_align_kernel<<<GRID_CTAS, 256>>>(boxes, fpn, (float*)d_out);
}

// round 7
// speedup vs baseline: 1.0251x; 1.0131x over previous
#include <cuda_runtime.h>

#define CROP 14
#define B_ 4
#define N_ 256
#define H_ 256
#define W_ 256
#define C_ 256
#define CQ (C_ / 4)            // float4 quads per pixel = 64

#define NPOS (CROP * CROP)     // 196 positions per box
#define NBOX (B_ * N_)         // 1024 boxes
#define TOTAL_POS (NBOX * NPOS)

// 196 positions per box, split across 7 CTAs of 28 positions each.
#define PARTS 7
#define POS_PER_PART 28

// Precomputed per-position gather data (prep kernel -> stream kernel).
__device__ int4   g_off[TOTAL_POS];   // (tl, tr, bl, br) in float4 units
__device__ float4 g_wv [TOTAL_POS];   // (w00, w01, w10, w11), validity folded in

// ---------------------------------------------------------------------------
// Kernel 1: per-position offsets + weights. One thread per (box, position).
// ---------------------------------------------------------------------------
__device__ __forceinline__ void axis_sample(float lo, float hi, int i,
                                            int& i0, int& i1, float& w, float& v)
{
    // Replicate reference math in float32:
    //   n1 = lo/255 ; n2 = (hi-1)/255 ; t = i/13 ; s = (n1 + (n2-n1)*t) * 255
    const float t  = (float)i / 13.0f;
    const float n1 = lo / 255.0f;
    const float n2 = (hi - 1.0f) / 255.0f;
    const float s  = (n1 + (n2 - n1) * t) * 255.0f;
    v = (s >= 0.0f && s <= 255.0f) ? 1.0f : 0.0f;
    const float f0 = floorf(s);
    w = s - f0;
    i0 = (int)f0;
    i1 = i0 + 1;
    i0 = min(max(i0, 0), H_ - 1);
    i1 = min(max(i1, 0), H_ - 1);
}

__global__ __launch_bounds__(256) void roi_prep_kernel(
    const float* __restrict__ boxes)
{
    const int gp = blockIdx.x * blockDim.x + threadIdx.x;
    if (gp >= TOTAL_POS) return;

    const int blk = gp / NPOS;           // box index: b * N_ + n
    const int pos = gp - blk * NPOS;
    const int py  = pos / CROP;
    const int px  = pos - py * CROP;

    const float4 bx = __ldg(&((const float4*)boxes)[blk]);   // (x1,y1,x2,y2)

    int y0, y1; float wy, vy;
    int x0, x1; float wx, vx;
    axis_sample(bx.y, bx.w, py, y0, y1, wy, vy);
    axis_sample(bx.x, bx.z, px, x0, x1, wx, vx);

    const float v = vy * vx;
    g_off[gp] = make_int4((y0 * W_ + x0) * CQ, (y0 * W_ + x1) * CQ,
                          (y1 * W_ + x0) * CQ, (y1 * W_ + x1) * CQ);
    g_wv[gp]  = make_float4((1.0f - wy) * (1.0f - wx) * v,
                            (1.0f - wy) * wx * v,
                            wy * (1.0f - wx) * v,
                            wy * wx * v);
}

// ---------------------------------------------------------------------------
// Kernel 2: pure streaming gather — no smem, no barriers, no setup phase.
// ---------------------------------------------------------------------------
__global__ __launch_bounds__(256) void roi_stream_kernel(
    const float* __restrict__ fpn,
    float* __restrict__ out)
{
    const int blk  = blockIdx.y;       // box index (box-major for L2 locality)
    const int part = blockIdx.x;       // 0..6
    const int b    = blk >> 8;         // N_ = 256
    const int base = part * POS_PER_PART;
    const int gp0  = blk * NPOS + base;

    const int tid = threadIdx.x;
    const int sub = tid >> 6;   // 4 positions in flight across the CTA
    const int q   = tid & 63;   // float4 index within C

    const float4* img  = (const float4*)(fpn) + (size_t)b * (H_ * W_ * CQ);
    float4*       outp = (float4*)(out) + ((size_t)blk * NPOS + base) * CQ;

    #pragma unroll
    for (int pb = 0; pb < POS_PER_PART; pb += 4) {
        const int p = pb + sub;
        // 64 threads read the same 32B -> L1 broadcast; L2-resident after prep.
        const int4   o = __ldg(&g_off[gp0 + p]);
        const float4 w = __ldg(&g_wv [gp0 + p]);

        const float4 tl = img[o.x + q];
        const float4 tr = img[o.y + q];
        const float4 bl = img[o.z + q];
        const float4 br = img[o.w + q];

        float4 r;
        r.x = tl.x * w.x + tr.x * w.y + bl.x * w.z + br.x * w.w;
        r.y = tl.y * w.x + tr.y * w.y + bl.y * w.z + br.y * w.w;
        r.z = tl.z * w.x + tr.z * w.y + bl.z * w.z + br.z * w.w;
        r.w = tl.w * w.x + tr.w * w.y + bl.w * w.z + br.w * w.w;

        // Streaming store: output is never re-read; keep the image L2-resident.
        __stcs(&outp[p * CQ + q], r);
    }
}

extern "C" void kernel_launch(void* const* d_in, const int* in_sizes, int n_in,
                              void* d_out, int out_size) {
    const float* boxes = (const float*)d_in[0];
    const float* fpn   = (const float*)d_in[1];
    if (n_in >= 2 && in_sizes[0] > in_sizes[1]) {
        boxes = (const float*)d_in[1];
        fpn   = (const float*)d_in[0];
    }
    roi_prep_kernel<<<(TOTAL_POS + 255) / 256, 256>>>(boxes);
    dim3 grid(PARTS, NBOX);
    roi_stream_kernel<<<grid, 256>>>(fpn, (float*)d_out);
}

// round 8
// speedup vs baseline: 1.0939x; 1.0671x over previous
#include <cuda_runtime.h>

#define CROP 14
#define B_ 4
#define N_ 256
#define H_ 256
#define W_ 256
#define C_ 256
#define CQ (C_ / 4)          // float4 quads per pixel = 64

// 196 positions per box, split across 4 CTAs of 49 positions each.
// Fewer/larger parts amortize the per-CTA setup over more streaming.
#define PARTS 4
#define POS_PER_PART 49
#define POS_PAD 52           // padded to a multiple of 4 for the group loop

__device__ __forceinline__ void axis_sample(float lo, float hi, int i,
                                            int& i0, int& i1, float& w, float& v)
{
    // Replicate reference math in float32:
    //   n1 = lo/255 ; n2 = (hi-1)/255 ; t = i/13 ; s = (n1 + (n2-n1)*t) * 255
    const float t  = (float)i / 13.0f;
    const float n1 = lo / 255.0f;
    const float n2 = (hi - 1.0f) / 255.0f;
    const float s  = (n1 + (n2 - n1) * t) * 255.0f;
    v = (s >= 0.0f && s <= 255.0f) ? 1.0f : 0.0f;
    const float f0 = floorf(s);
    w = s - f0;
    i0 = (int)f0;
    i1 = i0 + 1;
    i0 = min(max(i0, 0), H_ - 1);
    i1 = min(max(i1, 0), H_ - 1);
}

__global__ __launch_bounds__(256) void roi_align_kernel(
    const float* __restrict__ boxes,
    const float* __restrict__ fpn,
    float* __restrict__ out)
{
    // Per-position packed corner offsets (float4 units) + combined weights.
    __shared__ int4   s_off[POS_PAD];   // (tl, tr, bl, br)
    __shared__ float4 s_wv [POS_PAD];   // (w00, w01, w10, w11)

    const int blk  = blockIdx.y;       // box index: b * N_ + n (box-major)
    const int part = blockIdx.x;       // 0..3
    const int b    = blk >> 8;         // N_ = 256
    const int base = part * POS_PER_PART;

    const int tid = threadIdx.x;

    // Single-phase setup, ONE barrier: each of 49 threads computes its own
    // position's corner offsets + weights directly from the box.
    if (tid < POS_PAD) {
        if (tid < POS_PER_PART) {
            const float4 bx = ((const float4*)boxes)[blk];   // (x1, y1, x2, y2)
            const int pos = base + tid;
            const int py  = pos / CROP;
            const int px  = pos - py * CROP;

            int y0, y1; float wy, vy;
            int x0, x1; float wx, vx;
            axis_sample(bx.y, bx.w, py, y0, y1, wy, vy);
            axis_sample(bx.x, bx.z, px, x0, x1, wx, vx);

            const float v = vy * vx;
            s_off[tid] = make_int4((y0 * W_ + x0) * CQ, (y0 * W_ + x1) * CQ,
                                   (y1 * W_ + x0) * CQ, (y1 * W_ + x1) * CQ);
            s_wv[tid]  = make_float4((1.0f - wy) * (1.0f - wx) * v,
                                     (1.0f - wy) * wx * v,
                                     wy * (1.0f - wx) * v,
                                     wy * wx * v);
        } else {
            // Pads: safe zero-offset loads; the store for these is guarded.
            s_off[tid] = make_int4(0, 0, 0, 0);
            s_wv[tid]  = make_float4(0.f, 0.f, 0.f, 0.f);
        }
    }
    __syncthreads();

    const float4* img  = (const float4*)(fpn) + (size_t)b * (H_ * W_ * CQ);
    float4*       outp = (float4*)(out) + ((size_t)blk * (CROP * CROP) + base) * CQ;

    const int sub = tid >> 6;   // 4 positions in flight across the CTA
    const int q   = tid & 63;   // float4 index within C

    #pragma unroll 2
    for (int pb = 0; pb < POS_PAD; pb += 4) {
        const int p = pb + sub;
        const int4   o = s_off[p];
        const float4 w = s_wv[p];

        const float4 tl = img[o.x + q];
        const float4 tr = img[o.y + q];
        const float4 bl = img[o.z + q];
        const float4 br = img[o.w + q];

        float4 r;
        r.x = tl.x * w.x + tr.x * w.y + bl.x * w.z + br.x * w.w;
        r.y = tl.y * w.x + tr.y * w.y + bl.y * w.z + br.y * w.w;
        r.z = tl.z * w.x + tr.z * w.y + bl.z * w.z + br.z * w.w;
        r.w = tl.w * w.x + tr.w * w.y + bl.w * w.z + br.w * w.w;

        // Streaming store: output is never re-read; keep the image L2-resident.
        if (p < POS_PER_PART)
            __stcs(&outp[p * CQ + q], r);
    }
}

extern "C" void kernel_launch(void* const* d_in, const int* in_sizes, int n_in,
                              void* d_out, int out_size) {
    const float* boxes = (const float*)d_in[0];
    const float* fpn   = (const float*)d_in[1];
    if (n_in >= 2 && in_sizes[0] > in_sizes[1]) {
        boxes = (const float*)d_in[1];
        fpn   = (const float*)d_in[0];
    }
    dim3 grid(PARTS, B_ * N_);
    roi_align_kernel<<<grid, 256>>>(boxes, fpn, (float*)d_out);
}

// round 9
// speedup vs baseline: 1.1742x; 1.0734x over previous
#include <cuda_runtime.h>

#define CROP 14
#define B_ 4
#define N_ 256
#define H_ 256
#define W_ 256
#define C_ 256
#define CQ (C_ / 4)            // float4 quads per pixel = 64

#define NPOS (CROP * CROP)     // 196 positions per box
#define NBOX (B_ * N_)         // 1024 boxes
#define TOTAL_POS (NBOX * NPOS)

// 196 positions per box, split across 7 CTAs of 28 positions each.
#define PARTS 7
#define POS_PER_PART 28

// Precomputed per-position gather data (prep kernel -> stream kernel).
__device__ int4   g_off[TOTAL_POS];   // (tl, tr, bl, br) in float4 units
__device__ float4 g_wv [TOTAL_POS];   // (w00, w01, w10, w11), validity folded in

// ---------------------------------------------------------------------------
// Kernel 1: per-position offsets + weights. One thread per (box, position).
// (Numerics identical to the reference path; proven in round 7.)
// ---------------------------------------------------------------------------
__device__ __forceinline__ void axis_sample(float lo, float hi, int i,
                                            int& i0, int& i1, float& w, float& v)
{
    // Replicate reference math in float32:
    //   n1 = lo/255 ; n2 = (hi-1)/255 ; t = i/13 ; s = (n1 + (n2-n1)*t) * 255
    const float t  = (float)i / 13.0f;
    const float n1 = lo / 255.0f;
    const float n2 = (hi - 1.0f) / 255.0f;
    const float s  = (n1 + (n2 - n1) * t) * 255.0f;
    v = (s >= 0.0f && s <= 255.0f) ? 1.0f : 0.0f;
    const float f0 = floorf(s);
    w = s - f0;
    i0 = (int)f0;
    i1 = i0 + 1;
    i0 = min(max(i0, 0), H_ - 1);
    i1 = min(max(i1, 0), H_ - 1);
}

__global__ __launch_bounds__(256) void roi_prep_kernel(
    const float* __restrict__ boxes)
{
    const int gp = blockIdx.x * blockDim.x + threadIdx.x;   // grid exactly covers TOTAL_POS
    const int blk = gp / NPOS;           // box index: b * N_ + n
    const int pos = gp - blk * NPOS;
    const int py  = pos / CROP;
    const int px  = pos - py * CROP;

    const float4 bx = __ldg(&((const float4*)boxes)[blk]);   // (x1,y1,x2,y2)

    int y0, y1; float wy, vy;
    int x0, x1; float wx, vx;
    axis_sample(bx.y, bx.w, py, y0, y1, wy, vy);
    axis_sample(bx.x, bx.z, px, x0, x1, wx, vx);

    const float v = vy * vx;
    g_off[gp] = make_int4((y0 * W_ + x0) * CQ, (y0 * W_ + x1) * CQ,
                          (y1 * W_ + x0) * CQ, (y1 * W_ + x1) * CQ);
    g_wv[gp]  = make_float4((1.0f - wy) * (1.0f - wx) * v,
                            (1.0f - wy) * wx * v,
                            wy * (1.0f - wx) * v,
                            wy * wx * v);
}

// ---------------------------------------------------------------------------
// Kernel 2: round-2 champion streaming body; setup is a 896-byte smem fill.
// ---------------------------------------------------------------------------
__global__ __launch_bounds__(256) void roi_stream_kernel(
    const float* __restrict__ fpn,
    float* __restrict__ out)
{
    __shared__ int4   s_off[POS_PER_PART];   // (tl, tr, bl, br)
    __shared__ float4 s_wv [POS_PER_PART];   // (w00, w01, w10, w11)

    const int blk  = blockIdx.y;       // box index: b * N_ + n (box-major)
    const int part = blockIdx.x;       // 0..6
    const int b    = blk >> 8;         // N_ = 256
    const int base = part * POS_PER_PART;
    const int gp0  = blk * NPOS + base;

    const int tid = threadIdx.x;

    // Minimal setup: copy this CTA's precomputed 896B from L2 into smem.
    if (tid < POS_PER_PART) {
        s_off[tid] = __ldg(&g_off[gp0 + tid]);
    } else if (tid < 2 * POS_PER_PART) {
        s_wv[tid - POS_PER_PART] = __ldg(&g_wv[gp0 + tid - POS_PER_PART]);
    }
    __syncthreads();

    const float4* img  = (const float4*)(fpn) + (size_t)b * (H_ * W_ * CQ);
    float4*       outp = (float4*)(out) + ((size_t)blk * NPOS + base) * CQ;

    const int sub = tid >> 6;   // 4 positions in flight across the CTA
    const int q   = tid & 63;   // float4 index within C

    #pragma unroll 2
    for (int pb = 0; pb < POS_PER_PART; pb += 4) {
        const int p = pb + sub;
        const int4   o = s_off[p];
        const float4 w = s_wv[p];

        const float4 tl = img[o.x + q];
        const float4 tr = img[o.y + q];
        const float4 bl = img[o.z + q];
        const float4 br = img[o.w + q];

        float4 r;
        r.x = tl.x * w.x + tr.x * w.y + bl.x * w.z + br.x * w.w;
        r.y = tl.y * w.x + tr.y * w.y + bl.y * w.z + br.y * w.w;
        r.z = tl.z * w.x + tr.z * w.y + bl.z * w.z + br.z * w.w;
        r.w = tl.w * w.x + tr.w * w.y + bl.w * w.z + br.w * w.w;

        // Streaming store: output is never re-read; keep the image L2-resident.
        __stcs(&outp[p * CQ + q], r);
    }
}

extern "C" void kernel_launch(void* const* d_in, const int* in_sizes, int n_in,
                              void* d_out, int out_size) {
    const float* boxes = (const float*)d_in[0];
    const float* fpn   = (const float*)d_in[1];
    if (n_in >= 2 && in_sizes[0] > in_sizes[1]) {
        boxes = (const float*)d_in[1];
        fpn   = (const float*)d_in[0];
    }
    roi_prep_kernel<<<TOTAL_POS / 256, 256>>>(boxes);   // 784 CTAs, exact cover
    dim3 grid(PARTS, NBOX);
    roi_stream_kernel<<<grid, 256>>>(fpn, (float*)d_out);
}

// round 10
// speedup vs baseline: 1.2488x; 1.0635x over previous
#include <cuda_runtime.h>

#define CROP 14
#define B_ 4
#define N_ 256
#define H_ 256
#define W_ 256
#define C_ 256
#define CQ (C_ / 4)          // float4 quads per pixel = 64

// 196 positions per box, split across 7 CTAs of 28 positions each.
#define PARTS 7
#define POS_PER_PART 28

__device__ __forceinline__ void axis_sample(float lo, float hi, int i,
                                            int& i0, int& i1, float& w, float& v)
{
    // Replicate reference math in float32:
    //   n1 = lo/255 ; n2 = (hi-1)/255 ; t = i/13 ; s = (n1 + (n2-n1)*t) * 255
    const float t  = (float)i / 13.0f;
    const float n1 = lo / 255.0f;
    const float n2 = (hi - 1.0f) / 255.0f;
    const float s  = (n1 + (n2 - n1) * t) * 255.0f;
    v = (s >= 0.0f && s <= 255.0f) ? 1.0f : 0.0f;
    const float f0 = floorf(s);
    w = s - f0;
    i0 = (int)f0;
    i1 = i0 + 1;
    i0 = min(max(i0, 0), H_ - 1);
    i1 = min(max(i1, 0), H_ - 1);
}

__global__ __launch_bounds__(256) void roi_align_kernel(
    const float* __restrict__ boxes,
    const float* __restrict__ fpn,
    float* __restrict__ out)
{
    // Per-position packed corner offsets (float4 units) + combined weights.
    __shared__ int4   s_off[POS_PER_PART];   // (tl, tr, bl, br)
    __shared__ float4 s_wv [POS_PER_PART];   // (w00, w01, w10, w11)

    const int blk  = blockIdx.y;       // box index: b * N_ + n (box-major)
    const int part = blockIdx.x;       // 0..6
    const int b    = blk >> 8;         // N_ = 256
    const int base = part * POS_PER_PART;

    const int tid = threadIdx.x;

    // Single-phase setup, ONE barrier: each of 28 threads computes its own
    // position's corner offsets + weights directly from the box. The
    // duplicated per-row/col axis math across threads is free (issue-bound
    // ALU headroom), and this removes round-2's second phase + barrier.
    if (tid < POS_PER_PART) {
        const float4 bx = ((const float4*)boxes)[blk];   // (x1, y1, x2, y2)
        const int pos = base + tid;
        const int py  = pos / CROP;
        const int px  = pos - py * CROP;

        int y0, y1; float wy, vy;
        int x0, x1; float wx, vx;
        axis_sample(bx.y, bx.w, py, y0, y1, wy, vy);
        axis_sample(bx.x, bx.z, px, x0, x1, wx, vx);

        const float v = vy * vx;
        s_off[tid] = make_int4((y0 * W_ + x0) * CQ, (y0 * W_ + x1) * CQ,
                               (y1 * W_ + x0) * CQ, (y1 * W_ + x1) * CQ);
        s_wv[tid]  = make_float4((1.0f - wy) * (1.0f - wx) * v,
                                 (1.0f - wy) * wx * v,
                                 wy * (1.0f - wx) * v,
                                 wy * wx * v);
    }
    __syncthreads();

    const float4* img  = (const float4*)(fpn) + (size_t)b * (H_ * W_ * CQ);
    float4*       outp = (float4*)(out) + ((size_t)blk * (CROP * CROP) + base) * CQ;

    const int sub = tid >> 6;   // 4 positions in flight across the CTA
    const int q   = tid & 63;   // float4 index within C

    #pragma unroll 2
    for (int pb = 0; pb < POS_PER_PART; pb += 4) {
        const int p = pb + sub;
        const int4   o = s_off[p];
        const float4 w = s_wv[p];

        const float4 tl = img[o.x + q];
        const float4 tr = img[o.y + q];
        const float4 bl = img[o.z + q];
        const float4 br = img[o.w + q];

        float4 r;
        r.x = tl.x * w.x + tr.x * w.y + bl.x * w.z + br.x * w.w;
        r.y = tl.y * w.x + tr.y * w.y + bl.y * w.z + br.y * w.w;
        r.z = tl.z * w.x + tr.z * w.y + bl.z * w.z + br.z * w.w;
        r.w = tl.w * w.x + tr.w * w.y + bl.w * w.z + br.w * w.w;

        // Streaming store: output is never re-read; keep the image L2-resident.
        __stcs(&outp[p * CQ + q], r);
    }
}

extern "C" void kernel_launch(void* const* d_in, const int* in_sizes, int n_in,
                              void* d_out, int out_size) {
    const float* boxes = (const float*)d_in[0];
    const float* fpn   = (const float*)d_in[1];
    if (n_in >= 2 && in_sizes[0] > in_sizes[1]) {
        boxes = (const float*)d_in[1];
        fpn   = (const float*)d_in[0];
    }
    dim3 grid(PARTS, B_ * N_);
    roi_align_kernel<<<grid, 256>>>(boxes, fpn, (float*)d_out);
}